// round 1
// baseline (speedup 1.0000x reference)
#include <cuda_runtime.h>
#include <math_constants.h>

// Problem constants (B=2, H=8 -> BH=16; N=16384; D=64; M=266)
#define BH   16
#define NSEQ 16384
#define DDIM 64
#define MDIM 266
#define MP   272      // padded M stride for scratch (16B-aligned rows)
#define MPAD 320      // padded M for context (5 chunks of 64)
#define NT   256      // NSEQ/64 row tiles
#define NSPLIT 16     // deterministic split-K over N for context

__device__ __align__(16) float g_ddk[(size_t)BH * NSEQ * MP];      // dd_k - diag_k
__device__ float g_headmax[BH];
__device__ __align__(16) float g_ctx_part[(size_t)BH * NSPLIT * MPAD * DDIM];
__device__ float g_ksum_part[BH * NSPLIT * MPAD];
__device__ __align__(16) float g_ctx[BH * MPAD * DDIM];
__device__ float g_ksum[BH * MPAD];

__device__ __forceinline__ float dn_const()    { return 0.35355339059327379f; }  // 64^-0.25
__device__ __forceinline__ float ratio_const() { return 0.06131393394849658f; }  // 266^-0.5
#define EPSV 1e-4f

__device__ __forceinline__ void atomicMaxFloat(float* addr, float val) {
    int* ai = (int*)addr;
    int old = *ai;
    while (__int_as_float(old) < val) {
        int prev = atomicCAS(ai, old, __float_as_int(val));
        if (prev == old) return;
        old = prev;
    }
}

__global__ void init_kernel() {
    if (threadIdx.x < BH) g_headmax[threadIdx.x] = -CUDART_INF_F;
}

// ---------------------------------------------------------------------------
// Pass 1: dd_k tile GEMM. Stores (dd - diag) to scratch; per-head max of dd.
// grid = BH * NT blocks of 256 threads. 64x266 output per block, k-dim 64.
// ---------------------------------------------------------------------------
__global__ __launch_bounds__(256) void pass1_k(const float* __restrict__ kin,
                                               const float* __restrict__ proj) {
    __shared__ float sK[64 * 65];
    __shared__ float sP[64 * 65];
    __shared__ float sdiag[64];
    __shared__ float swred[8];
    const int tid = threadIdx.x, tx = tid & 15, ty = tid >> 4;
    const int bh = blockIdx.x >> 8, nt = blockIdx.x & 255;
    const float* kb = kin + ((size_t)(bh * NSEQ + nt * 64)) * DDIM;

    for (int e = tid; e < 4096; e += 256) {
        int n = e >> 6, d = e & 63;
        sK[n * 65 + d] = kb[e] * dn_const();
    }
    __syncthreads();
    if (tid < 64) {
        float s = 0.f;
        #pragma unroll
        for (int d = 0; d < 64; d++) { float vv = sK[tid * 65 + d]; s = fmaf(vv, vv, s); }
        sdiag[tid] = 0.5f * s;   // 0.5 * dn^2 * sum(x^2) via pre-scaled rows
    }

    float tmax = -CUDART_INF_F;
    const size_t rb = ((size_t)(bh * NSEQ + nt * 64)) * MP;

    for (int mc = 0; mc < 5; mc++) {
        const int m0 = mc * 64;
        __syncthreads();
        for (int e = tid; e < 4096; e += 256) {
            int mm = e >> 6, d = e & 63;
            int m = m0 + mm;
            sP[mm * 65 + d] = (m < MDIM) ? proj[m * DDIM + d] : 0.f;
        }
        __syncthreads();

        float acc[4][4] = {};
        #pragma unroll 16
        for (int kk = 0; kk < 64; kk++) {
            float a[4], b[4];
            #pragma unroll
            for (int i = 0; i < 4; i++) a[i] = sK[(ty * 4 + i) * 65 + kk];
            #pragma unroll
            for (int j = 0; j < 4; j++) b[j] = sP[(tx * 4 + j) * 65 + kk];
            #pragma unroll
            for (int i = 0; i < 4; i++)
                #pragma unroll
                for (int j = 0; j < 4; j++)
                    acc[i][j] = fmaf(a[i], b[j], acc[i][j]);
        }

        if (mc < 4) {
            #pragma unroll
            for (int i = 0; i < 4; i++) {
                int row = ty * 4 + i;
                float dg = sdiag[row];
                tmax = fmaxf(tmax, fmaxf(fmaxf(acc[i][0], acc[i][1]),
                                         fmaxf(acc[i][2], acc[i][3])));
                float4 vv = make_float4(acc[i][0] - dg, acc[i][1] - dg,
                                        acc[i][2] - dg, acc[i][3] - dg);
                *reinterpret_cast<float4*>(&g_ddk[rb + (size_t)row * MP + m0 + tx * 4]) = vv;
            }
        } else {
            #pragma unroll
            for (int i = 0; i < 4; i++) {
                int row = ty * 4 + i;
                float dg = sdiag[row];
                #pragma unroll
                for (int j = 0; j < 4; j++) {
                    int m = m0 + tx * 4 + j;
                    if (m < MDIM) {
                        tmax = fmaxf(tmax, acc[i][j]);
                        g_ddk[rb + (size_t)row * MP + m] = acc[i][j] - dg;
                    }
                }
            }
        }
    }

    #pragma unroll
    for (int off = 16; off; off >>= 1)
        tmax = fmaxf(tmax, __shfl_xor_sync(0xffffffffu, tmax, off));
    if ((tid & 31) == 0) swred[tid >> 5] = tmax;
    __syncthreads();
    if (tid == 0) {
        float m = swred[0];
        #pragma unroll
        for (int w = 1; w < 8; w++) m = fmaxf(m, swred[w]);
        atomicMaxFloat(&g_headmax[bh], m);
    }
}

// ---------------------------------------------------------------------------
// Pass 2a: kp = ratio*(exp(scratch - stab)+eps); partial context kp^T v and
// partial ksum over a fixed 1024-row N split. Deterministic (no float atomics).
// grid = BH * 5 * NSPLIT
// ---------------------------------------------------------------------------
__global__ __launch_bounds__(256) void pass2a(const float* __restrict__ vin) {
    __shared__ float sKP[64 * 65];
    __shared__ float sV[64 * 65];
    const int tid = threadIdx.x, tx = tid & 15, ty = tid >> 4;
    const int split = blockIdx.x & 15;
    const int mc = (blockIdx.x >> 4) % 5;
    const int bh = blockIdx.x / 80;
    const float stab = g_headmax[bh];
    const int m0 = mc * 64;

    float acc[4][4] = {};
    float ksl = 0.f;

    for (int t = 0; t < 16; t++) {
        const int nb = split * 1024 + t * 64;
        __syncthreads();
        for (int e = tid; e < 4096; e += 256) {
            int nn = e >> 6, c = e & 63;
            size_t nrow = (size_t)(bh * NSEQ + nb + nn);
            float kp = 0.f;
            int m = m0 + c;
            if (m < MDIM) {
                float x = g_ddk[nrow * MP + m];
                kp = ratio_const() * (__expf(x - stab) + EPSV);
            }
            sKP[nn * 65 + c] = kp;
            sV[nn * 65 + c] = vin[nrow * DDIM + c];
        }
        __syncthreads();
        if (tid < 64) {
            #pragma unroll
            for (int nn = 0; nn < 64; nn++) ksl += sKP[nn * 65 + tid];
        }
        #pragma unroll 8
        for (int nn = 0; nn < 64; nn++) {
            float a[4], b[4];
            #pragma unroll
            for (int i = 0; i < 4; i++) a[i] = sKP[nn * 65 + ty * 4 + i];
            #pragma unroll
            for (int j = 0; j < 4; j++) b[j] = sV[nn * 65 + tx * 4 + j];
            #pragma unroll
            for (int i = 0; i < 4; i++)
                #pragma unroll
                for (int j = 0; j < 4; j++)
                    acc[i][j] = fmaf(a[i], b[j], acc[i][j]);
        }
    }

    const size_t pb = (size_t)(bh * NSPLIT + split) * (MPAD * DDIM);
    #pragma unroll
    for (int i = 0; i < 4; i++) {
        int m = m0 + ty * 4 + i;
        *reinterpret_cast<float4*>(&g_ctx_part[pb + (size_t)m * DDIM + tx * 4]) =
            make_float4(acc[i][0], acc[i][1], acc[i][2], acc[i][3]);
    }
    if (tid < 64)
        g_ksum_part[(bh * NSPLIT + split) * MPAD + m0 + tid] = ksl;
}

// ---------------------------------------------------------------------------
// Pass 2b: reduce split-K partials (fixed order -> deterministic).
// ---------------------------------------------------------------------------
__global__ __launch_bounds__(256) void pass2b() {
    int gid = blockIdx.x * 256 + threadIdx.x;
    if (gid < BH * MPAD * DDIM) {
        int bh = gid / (MPAD * DDIM);
        int rem = gid - bh * (MPAD * DDIM);
        float s = 0.f;
        #pragma unroll
        for (int sp = 0; sp < NSPLIT; sp++)
            s += g_ctx_part[(size_t)(bh * NSPLIT + sp) * (MPAD * DDIM) + rem];
        g_ctx[gid] = s;
    }
    if (gid < BH * MPAD) {
        int bh = gid / MPAD, m = gid - bh * MPAD;
        float s = 0.f;
        #pragma unroll
        for (int sp = 0; sp < NSPLIT; sp++)
            s += g_ksum_part[(bh * NSPLIT + sp) * MPAD + m];
        g_ksum[gid] = s;
    }
}

// ---------------------------------------------------------------------------
// Pass 3: fused q side. dd_q GEMM -> row max -> exp -> qp@context + denom.
// grid = BH * NT, dynamic smem.
// ---------------------------------------------------------------------------
template <int MEND>
__device__ __forceinline__ void gemm2_chunk(const float* sDD, const float* sPC,
                                            int ty, int tx, int m0, float oacc[4][4]) {
    #pragma unroll
    for (int mm = 0; mm < MEND; mm++) {
        float a[4], b[4];
        #pragma unroll
        for (int i = 0; i < 4; i++) a[i] = sDD[(ty * 4 + i) * 273 + m0 + mm];
        #pragma unroll
        for (int j = 0; j < 4; j++) b[j] = sPC[mm * 65 + tx * 4 + j];
        #pragma unroll
        for (int i = 0; i < 4; i++)
            #pragma unroll
            for (int j = 0; j < 4; j++)
                oacc[i][j] = fmaf(a[i], b[j], oacc[i][j]);
    }
}

__global__ __launch_bounds__(256) void pass3_q(const float* __restrict__ qin,
                                               const float* __restrict__ proj,
                                               float* __restrict__ out) {
    extern __shared__ float sm[];
    float* sQ    = sm;            // 64*65 = 4160
    float* sPC   = sm + 4160;     // 64*65 = 4160 (proj chunk, later ctx chunk)
    float* sDD   = sm + 8320;     // 64*273 = 17472
    float* sKs   = sm + 25792;    // 272
    float* sdiag = sm + 26064;    // 64
    float* srmax = sm + 26128;    // 64
    float* sden  = sm + 26192;    // 64    (total 26256 floats = 105024 B)

    const int tid = threadIdx.x, tx = tid & 15, ty = tid >> 4;
    const int bh = blockIdx.x >> 8, nt = blockIdx.x & 255;
    const float* qb = qin + ((size_t)(bh * NSEQ + nt * 64)) * DDIM;

    for (int e = tid; e < 4096; e += 256) {
        int n = e >> 6, d = e & 63;
        sQ[n * 65 + d] = qb[e] * dn_const();
    }
    for (int e = tid; e < MDIM; e += 256) sKs[e] = g_ksum[bh * MPAD + e];
    __syncthreads();
    if (tid < 64) {
        float s = 0.f;
        #pragma unroll
        for (int d = 0; d < 64; d++) { float vv = sQ[tid * 65 + d]; s = fmaf(vv, vv, s); }
        sdiag[tid] = 0.5f * s;
    }

    float rmax[4] = {-CUDART_INF_F, -CUDART_INF_F, -CUDART_INF_F, -CUDART_INF_F};

    for (int mc = 0; mc < 5; mc++) {
        const int m0 = mc * 64;
        __syncthreads();
        for (int e = tid; e < 4096; e += 256) {
            int mm = e >> 6, d = e & 63;
            int m = m0 + mm;
            sPC[mm * 65 + d] = (m < MDIM) ? proj[m * DDIM + d] : 0.f;
        }
        __syncthreads();

        float acc[4][4] = {};
        #pragma unroll 16
        for (int kk = 0; kk < 64; kk++) {
            float a[4], b[4];
            #pragma unroll
            for (int i = 0; i < 4; i++) a[i] = sQ[(ty * 4 + i) * 65 + kk];
            #pragma unroll
            for (int j = 0; j < 4; j++) b[j] = sPC[(tx * 4 + j) * 65 + kk];
            #pragma unroll
            for (int i = 0; i < 4; i++)
                #pragma unroll
                for (int j = 0; j < 4; j++)
                    acc[i][j] = fmaf(a[i], b[j], acc[i][j]);
        }
        #pragma unroll
        for (int i = 0; i < 4; i++) {
            float mv = -CUDART_INF_F;
            #pragma unroll
            for (int j = 0; j < 4; j++) {
                int m = m0 + tx * 4 + j;
                if (m < MDIM) {
                    sDD[(ty * 4 + i) * 273 + m] = acc[i][j];
                    mv = fmaxf(mv, acc[i][j]);
                }
            }
            #pragma unroll
            for (int off = 8; off; off >>= 1)
                mv = fmaxf(mv, __shfl_xor_sync(0xffffffffu, mv, off));
            rmax[i] = fmaxf(rmax[i], mv);
        }
    }
    if (tx == 0) {
        #pragma unroll
        for (int i = 0; i < 4; i++) srmax[ty * 4 + i] = rmax[i];
    }
    __syncthreads();

    // exp transform in place: qp = ratio*(exp(dd - diag - rowmax) + eps)
    for (int e = tid; e < 64 * 273; e += 256) {
        int n = e / 273, m = e - n * 273;
        float vv = 0.f;
        if (m < MDIM)
            vv = ratio_const() * (__expf(sDD[e] - sdiag[n] - srmax[n]) + EPSV);
        sDD[e] = vv;
    }
    __syncthreads();

    if (tid < 64) {
        float den = 0.f;
        for (int m = 0; m < MDIM; m++) den = fmaf(sDD[tid * 273 + m], sKs[m], den);
        sden[tid] = 1.f / den;
    }

    float oacc[4][4] = {};
    for (int mc = 0; mc < 5; mc++) {
        const int m0 = mc * 64;
        __syncthreads();
        for (int e = tid; e < 4096; e += 256) {
            int mm = e >> 6, d = e & 63;
            sPC[mm * 65 + d] = g_ctx[(size_t)(bh * MPAD + m0 + mm) * DDIM + d];
        }
        __syncthreads();
        if (mc < 4) gemm2_chunk<64>(sDD, sPC, ty, tx, m0, oacc);
        else        gemm2_chunk<10>(sDD, sPC, ty, tx, m0, oacc);
    }
    __syncthreads();

    float* ob = out + ((size_t)(bh * NSEQ + nt * 64)) * DDIM;
    #pragma unroll
    for (int i = 0; i < 4; i++) {
        int row = ty * 4 + i;
        float di = sden[row];
        *reinterpret_cast<float4*>(&ob[(size_t)row * DDIM + tx * 4]) =
            make_float4(oacc[i][0] * di, oacc[i][1] * di, oacc[i][2] * di, oacc[i][3] * di);
    }
}

// ---------------------------------------------------------------------------
extern "C" void kernel_launch(void* const* d_in, const int* in_sizes, int n_in,
                              void* d_out, int out_size) {
    const float* q    = (const float*)d_in[0];
    const float* k    = (const float*)d_in[1];
    const float* v    = (const float*)d_in[2];
    const float* proj = (const float*)d_in[3];
    float* out = (float*)d_out;

    cudaFuncSetAttribute(pass3_q, cudaFuncAttributeMaxDynamicSharedMemorySize, 26256 * 4);

    init_kernel<<<1, 32>>>();
    pass1_k<<<BH * NT, 256>>>(k, proj);
    pass2a<<<BH * 5 * NSPLIT, 256>>>(v);
    pass2b<<<(BH * MPAD * DDIM + 255) / 256, 256>>>();
    pass3_q<<<BH * NT, 256, 26256 * 4>>>(q, proj, out);
}